// round 14
// baseline (speedup 1.0000x reference)
#include <cuda_runtime.h>
#include <cuda_fp16.h>
#include <cstdint>

// ===================== Problem constants =====================
#define B_DIM 8192
#define P_DIM 24
#define Q_DIM 12
#define E_DIM 256
#define V_DIM 1000
#define LN_EPS 1e-5f

#define GEMM_CTAS 768          // 24 p * 32 mslots; each CTA: 4 tiles of 64 rows
#define CAT_CTAS 384
#define TOK_PER_CAT_CTA 256    // 98304 / 384

// fragment-packed W2: [p][ks(16)][ntp(16)][lane(32)] uint4  (3.1 MB)
__device__ uint4 g_W2Tf[P_DIM * 16 * 16 * 32];

// ===================== Prep kernel: W2 -> fragment-packed fp16 (direct) =====================
#define PREP_SMEM 65536
__global__ __launch_bounds__(256)
void prep_kernel(const float* __restrict__ W2) {
    extern __shared__ float sm[];          // [64][256] fp32 slice
    const int p  = blockIdx.x >> 2;
    const int sl = blockIdx.x & 3;
    const int e0 = sl * 64;
    const int tid = threadIdx.x;

    #pragma unroll 4
    for (int it = 0; it < 64; it++)
        sm[it * 256 + tid] = W2[((size_t)p * 256 + e0 + it) * 256 + tid];
    __syncthreads();

    const int lane = tid & 31;
    const int warp = tid >> 5;             // 0..7
    const int ksl  = warp & 3;
    const int ks   = sl * 4 + ksl;
    const int ntp0 = (warp >> 2) * 8;
    const int ne_b = lane >> 2;
    const int el0  = ksl * 16 + 2 * (lane & 3);   // local e of kh0 pair

    uint4* dstb = g_W2Tf + (size_t)p * 8192;
    #pragma unroll
    for (int j = 0; j < 8; j++) {
        const int ntp = ntp0 + j;
        const int ne = 2 * ntp * 8 + ne_b;
        const int no = ne + 8;
        uint4 v;
        __half2 h;
        h = __floats2half2_rn(sm[el0 * 256 + ne],       sm[(el0 + 1) * 256 + ne]);
        v.x = *reinterpret_cast<uint32_t*>(&h);
        h = __floats2half2_rn(sm[(el0 + 8) * 256 + ne], sm[(el0 + 9) * 256 + ne]);
        v.y = *reinterpret_cast<uint32_t*>(&h);
        h = __floats2half2_rn(sm[el0 * 256 + no],       sm[(el0 + 1) * 256 + no]);
        v.z = *reinterpret_cast<uint32_t*>(&h);
        h = __floats2half2_rn(sm[(el0 + 8) * 256 + no], sm[(el0 + 9) * 256 + no]);
        v.w = *reinterpret_cast<uint32_t*>(&h);
        dstb[(ks * 16 + ntp) * 32 + lane] = v;
    }
}

// ---- fast gelu (validated: rel_err identical to erff version) ----
__device__ __forceinline__ float fast_gelu(float t) {
    const float z  = fabsf(t) * 0.70710678118654752f;
    const float k  = __fdividef(1.0f, fmaf(0.3275911f, z, 1.0f));
    float pk = fmaf(1.061405429f, k, -1.453152027f);
    pk = fmaf(pk, k, 1.421413741f);
    pk = fmaf(pk, k, -0.284496736f);
    pk = fmaf(pk, k, 0.254829592f);
    pk = pk * k;
    const float ez   = __expf(-z * z);
    const float erfv = fmaf(-pk, ez, 1.0f);
    const float e    = (t >= 0.f) ? erfv : -erfv;
    return 0.5f * t * (1.0f + e);
}

// ===================== Fused kernel: 256 threads, 2 CTAs/SM =====================
// SMEM byte offsets
#define SM_X    0        // 256 f (all 4 tiles' xs)
#define SM_W1   1024     // 256 f
#define SM_B1   2048
#define SM_B2   3072
#define SM_G    4096
#define SM_BE   5120
#define SM_STAT 6144     // 64 rows x 16 f = 4096 B (ends 10240)
#define SM_A    12288    // 32768 B : A frags [ks(16)][mti(4)][lane(32)] uint4
#define SM_BUF  45056    // 2 x 32768 B : B ring, chunk = [ksl(4)][ntp(16)][lane(32)] uint4
#define GEMM_SMEM 110592

__device__ __forceinline__ void mma16816(float* c, const uint32_t* a, const uint32_t* b) {
    asm volatile(
        "mma.sync.aligned.m16n8k16.row.col.f32.f16.f16.f32 "
        "{%0,%1,%2,%3}, {%4,%5,%6,%7}, {%8,%9}, {%0,%1,%2,%3};\n"
        : "+f"(c[0]), "+f"(c[1]), "+f"(c[2]), "+f"(c[3])
        : "r"(a[0]), "r"(a[1]), "r"(a[2]), "r"(a[3]), "r"(b[0]), "r"(b[1]));
}

// stage full chunk c into buf (pre-loop use)
__device__ __forceinline__ void stage_full(const uint4* __restrict__ w2f, uint4* buf,
                                           int c, int warp, int lane) {
    const int ksl = warp & 3;
    const int ntp0 = (warp >> 2) * 8;
    const uint4* src = w2f + (size_t)(c * 4 + ksl) * 512 + ntp0 * 32 + lane;
    uint4* dst = buf + (ksl * 16 + ntp0) * 32 + lane;
    #pragma unroll
    for (int i = 0; i < 8; i++)
        dst[i * 32] = src[i * 32];
}

// Pipelined mma over chunk c (4 ks): A/B fragment double-buffer hides LDS latency
// under the HMMA block. Optionally stages chunk cs (gmem->smem) interleaved.
template <bool STAGE>
__device__ __forceinline__ void mma_chunk(float acc[4][4][4],
                                          const uint4* __restrict__ afrag,
                                          const uint4* __restrict__ bbuf,
                                          int c, int warp, int lane,
                                          const uint4* __restrict__ w2f,
                                          uint4* sbuf, int cs) {
    const int ksl_s = warp & 3;
    const int ntp0  = (warp >> 2) * 8;
    const uint4* src = w2f + (size_t)(cs * 4 + ksl_s) * 512 + ntp0 * 32 + lane;
    uint4* dst = sbuf + (ksl_s * 16 + ntp0) * 32 + lane;

    uint4 A[2][4], B[2][2];
    #pragma unroll
    for (int mti = 0; mti < 4; mti++)
        A[0][mti] = afrag[((c * 4 + 0) * 4 + mti) * 32 + lane];
    B[0][0] = bbuf[(warp * 2 + 0) * 32 + lane];
    B[0][1] = bbuf[(warp * 2 + 1) * 32 + lane];

    #pragma unroll
    for (int ksl = 0; ksl < 4; ksl++) {
        const int cur = ksl & 1, nxt = cur ^ 1;
        uint4 r0, r1;
        if (STAGE) {
            r0 = src[(2 * ksl) * 32];
            r1 = src[(2 * ksl + 1) * 32];
        }
        if (ksl < 3) {
            #pragma unroll
            for (int mti = 0; mti < 4; mti++)
                A[nxt][mti] = afrag[((c * 4 + ksl + 1) * 4 + mti) * 32 + lane];
            B[nxt][0] = bbuf[((ksl + 1) * 16 + warp * 2 + 0) * 32 + lane];
            B[nxt][1] = bbuf[((ksl + 1) * 16 + warp * 2 + 1) * 32 + lane];
        }
        #pragma unroll
        for (int i = 0; i < 2; i++) {
            uint32_t b0[2]  = {B[cur][i].x, B[cur][i].y};
            uint32_t b1r[2] = {B[cur][i].z, B[cur][i].w};
            #pragma unroll
            for (int mti = 0; mti < 4; mti++) {
                uint32_t a[4] = {A[cur][mti].x, A[cur][mti].y, A[cur][mti].z, A[cur][mti].w};
                mma16816(acc[mti][i * 2],     a, b0);
                mma16816(acc[mti][i * 2 + 1], a, b1r);
            }
        }
        if (STAGE) {
            dst[(2 * ksl) * 32] = r0;
            dst[(2 * ksl + 1) * 32] = r1;
        }
    }
}

__global__ __launch_bounds__(256, 2)
void fused_kernel(const float* __restrict__ x_num,
                  const int*   __restrict__ x_cat,
                  const float* __restrict__ W1,
                  const float* __restrict__ b1,
                  const float* __restrict__ b2,
                  const float* __restrict__ emb,
                  const float* __restrict__ gamma,
                  const float* __restrict__ beta,
                  float* __restrict__ out) {
    const int tid  = threadIdx.x;
    const int lane = tid & 31;
    const int warp = tid >> 5;       // 0..7

    // ================= CAT PATH: 2 independent tokens per warp-iter =================
    if (blockIdx.x >= GEMM_CTAS) {
        const int blk2 = blockIdx.x - GEMM_CTAS;
        const float4* g4  = (const float4*)gamma;
        const float4* be4 = (const float4*)beta;
        float4 g0 = g4[lane], g1 = g4[lane + 32];
        float4 e0 = be4[lane], e1 = be4[lane + 32];

        #pragma unroll 1
        for (int it = 0; it < TOK_PER_CAT_CTA / 16; it++) {
            const int tokA = blk2 * TOK_PER_CAT_CTA + it * 16 + warp * 2;
            const int tokB = tokA + 1;
            const int bA = tokA / Q_DIM, qA = tokA % Q_DIM;
            const int bB = tokB / Q_DIM, qB = tokB % Q_DIM;
            const int idxA = x_cat[(size_t)bA * Q_DIM + qA];
            const int idxB = x_cat[(size_t)bB * Q_DIM + qB];
            const float4* srcA = (const float4*)(emb + ((size_t)qA * V_DIM + idxA) * E_DIM);
            const float4* srcB = (const float4*)(emb + ((size_t)qB * V_DIM + idxB) * E_DIM);
            float4 a0 = srcA[lane], a1 = srcA[lane + 32];
            float4 c0 = srcB[lane], c1 = srcB[lane + 32];

            float sa = a0.x + a0.y + a0.z + a0.w + a1.x + a1.y + a1.z + a1.w;
            float qa = a0.x * a0.x + a0.y * a0.y + a0.z * a0.z + a0.w * a0.w
                     + a1.x * a1.x + a1.y * a1.y + a1.z * a1.z + a1.w * a1.w;
            float sb = c0.x + c0.y + c0.z + c0.w + c1.x + c1.y + c1.z + c1.w;
            float qb = c0.x * c0.x + c0.y * c0.y + c0.z * c0.z + c0.w * c0.w
                     + c1.x * c1.x + c1.y * c1.y + c1.z * c1.z + c1.w * c1.w;
            #pragma unroll
            for (int off = 16; off > 0; off >>= 1) {
                sa += __shfl_xor_sync(0xFFFFFFFFu, sa, off);
                qa += __shfl_xor_sync(0xFFFFFFFFu, qa, off);
                sb += __shfl_xor_sync(0xFFFFFFFFu, sb, off);
                qb += __shfl_xor_sync(0xFFFFFFFFu, qb, off);
            }
            const float muA = sa * (1.0f / 256.0f);
            const float rsA = rsqrtf(qa * (1.0f / 256.0f) - muA * muA + LN_EPS);
            const float muB = sb * (1.0f / 256.0f);
            const float rsB = rsqrtf(qb * (1.0f / 256.0f) - muB * muB + LN_EPS);

            float4 r0, r1;
            r0.x = (a0.x - muA) * rsA * g0.x + e0.x;
            r0.y = (a0.y - muA) * rsA * g0.y + e0.y;
            r0.z = (a0.z - muA) * rsA * g0.z + e0.z;
            r0.w = (a0.w - muA) * rsA * g0.w + e0.w;
            r1.x = (a1.x - muA) * rsA * g1.x + e1.x;
            r1.y = (a1.y - muA) * rsA * g1.y + e1.y;
            r1.z = (a1.z - muA) * rsA * g1.z + e1.z;
            r1.w = (a1.w - muA) * rsA * g1.w + e1.w;
            float4* dstA = (float4*)(out + ((size_t)bA * 36 + 24 + qA) * E_DIM);
            dstA[lane] = r0;
            dstA[lane + 32] = r1;

            r0.x = (c0.x - muB) * rsB * g0.x + e0.x;
            r0.y = (c0.y - muB) * rsB * g0.y + e0.y;
            r0.z = (c0.z - muB) * rsB * g0.z + e0.z;
            r0.w = (c0.w - muB) * rsB * g0.w + e0.w;
            r1.x = (c1.x - muB) * rsB * g1.x + e1.x;
            r1.y = (c1.y - muB) * rsB * g1.y + e1.y;
            r1.z = (c1.z - muB) * rsB * g1.z + e1.z;
            r1.w = (c1.w - muB) * rsB * g1.w + e1.w;
            float4* dstB = (float4*)(out + ((size_t)bB * 36 + 24 + qB) * E_DIM);
            dstB[lane] = r0;
            dstB[lane + 32] = r1;
        }
        return;
    }

    // ================= GEMM PATH =================
    extern __shared__ char smem[];
    const int p     = blockIdx.x >> 5;   // 0..23
    const int mslot = blockIdx.x & 31;   // 0..31

    float* xs_all = (float*)(smem + SM_X);            // [4][64]
    float* w1s = (float*)(smem + SM_W1);
    float* b1s = (float*)(smem + SM_B1);
    float* b2s = (float*)(smem + SM_B2);
    float* gs  = (float*)(smem + SM_G);
    float* bes = (float*)(smem + SM_BE);
    float* statb = (float*)(smem + SM_STAT);          // [64][16]
    uint4* afrag = (uint4*)(smem + SM_A);
    uint4* bufs[2] = { (uint4*)(smem + SM_BUF), (uint4*)(smem + SM_BUF + 32768) };

    xs_all[tid] = x_num[(size_t)(mslot * 256 + tid) * P_DIM + p];
    w1s[tid] = W1[p * 256 + tid];
    b1s[tid] = b1[p * 256 + tid];
    b2s[tid] = b2[p * 256 + tid];
    gs[tid]  = gamma[tid];
    bes[tid] = beta[tid];

    const uint4* w2f = g_W2Tf + (size_t)p * 8192;

    // pre-stage chunks 0 (buf0) and 1 (buf1)
    stage_full(w2f, bufs[0], 0, warp, lane);
    stage_full(w2f, bufs[1], 1, warp, lane);

    float2 b2v[4];
    #pragma unroll
    for (int ntl = 0; ntl < 4; ntl++)
        b2v[ntl] = *(float2*)&b2[p * 256 + warp * 32 + ntl * 8 + (lane & 3) * 2];

    __syncthreads();     // consts + xs + pre-staged bufs visible

    // ---- Tile loop: 4 tiles of 64 rows ----
    for (int t = 0; t < 4; t++) {
        const int m0 = (mslot * 4 + t) * 64;
        const int par = t & 1;
        const int o0 = par ? 2 : 0, o1 = par ? 3 : 1;
        const int o2 = par ? 0 : 2, o3 = par ? 1 : 3;
        const float* xs = xs_all + t * 64;

        // ---- Prologue: gelu -> A frags (warp covers ks = warp, warp+8) ----
        // (previous tile's A reads all complete: ordered by the stats barrier)
        #pragma unroll
        for (int kk = 0; kk < 2; kk++) {
            const int ks = warp + kk * 8;
            const int kbase = ks * 16 + (lane & 3) * 2;
            #pragma unroll
            for (int mti = 0; mti < 4; mti++) {
                const float xm0 = xs[mti * 16 + (lane >> 2)];
                const float xm1 = xs[mti * 16 + (lane >> 2) + 8];
                uint32_t r[4];
                #pragma unroll
                for (int reg = 0; reg < 4; reg++) {
                    const float xm = (reg & 1) ? xm1 : xm0;
                    const int k = kbase + (reg & 2) * 4;
                    float h0 = fast_gelu(fmaf(xm, w1s[k],     b1s[k]));
                    float h1 = fast_gelu(fmaf(xm, w1s[k + 1], b1s[k + 1]));
                    __half2 hv = __floats2half2_rn(h0, h1);
                    r[reg] = *reinterpret_cast<uint32_t*>(&hv);
                }
                afrag[(ks * 4 + mti) * 32 + lane] = make_uint4(r[0], r[1], r[2], r[3]);
            }
        }
        __syncthreads();                 // A ready

        float acc[4][4][4];
        #pragma unroll
        for (int i = 0; i < 4; i++)
            #pragma unroll
            for (int j = 0; j < 4; j++)
                #pragma unroll
                for (int r = 0; r < 4; r++) acc[i][j][r] = 0.f;

        mma_chunk<false>(acc, afrag, bufs[o0 & 1], o0, warp, lane, w2f, nullptr, 0);
        __syncthreads();                 // all warps done reading buf[o0&1]
        mma_chunk<true >(acc, afrag, bufs[o1 & 1], o1, warp, lane, w2f, bufs[o2 & 1], o2);
        __syncthreads();                 // buf[o2&1] staged; done reading buf[o1&1]
        mma_chunk<true >(acc, afrag, bufs[o2 & 1], o2, warp, lane, w2f, bufs[o3 & 1], o3);
        __syncthreads();                 // buf[o3&1] staged
        mma_chunk<false>(acc, afrag, bufs[o3 & 1], o3, warp, lane, w2f, nullptr, 0);

        // ---- Epilogue: +b2, LayerNorm ----
        #pragma unroll
        for (int mti = 0; mti < 4; mti++)
            #pragma unroll
            for (int ntl = 0; ntl < 4; ntl++) {
                acc[mti][ntl][0] += b2v[ntl].x;
                acc[mti][ntl][1] += b2v[ntl].y;
                acc[mti][ntl][2] += b2v[ntl].x;
                acc[mti][ntl][3] += b2v[ntl].y;
            }

        #pragma unroll
        for (int mti = 0; mti < 4; mti++)
            #pragma unroll
            for (int h = 0; h < 2; h++) {
                float s = 0.f, q = 0.f;
                #pragma unroll
                for (int ntl = 0; ntl < 4; ntl++) {
                    float v0 = acc[mti][ntl][h * 2];
                    float v1 = acc[mti][ntl][h * 2 + 1];
                    s += v0 + v1;
                    q += v0 * v0 + v1 * v1;
                }
                s += __shfl_xor_sync(0xFFFFFFFFu, s, 1);
                q += __shfl_xor_sync(0xFFFFFFFFu, q, 1);
                s += __shfl_xor_sync(0xFFFFFFFFu, s, 2);
                q += __shfl_xor_sync(0xFFFFFFFFu, q, 2);
                if ((lane & 3) == 0) {
                    const int row = mti * 16 + (lane >> 2) + h * 8;
                    *(float2*)&statb[row * 16 + warp * 2] = make_float2(s, q);
                }
            }
        __syncthreads();                 // stats visible (also orders A reads vs next prologue)

        #pragma unroll
        for (int mti = 0; mti < 4; mti++)
            #pragma unroll
            for (int h = 0; h < 2; h++) {
                const int row = mti * 16 + (lane >> 2) + h * 8;
                float sum = 0.f, sq = 0.f;
                #pragma unroll
                for (int j = 0; j < 4; j++) {
                    float4 v = *(float4*)&statb[row * 16 + j * 4];
                    sum += v.x + v.z;
                    sq  += v.y + v.w;
                }
                const float mu   = sum * (1.0f / 256.0f);
                const float var  = sq * (1.0f / 256.0f) - mu * mu;
                const float rstd = rsqrtf(var + LN_EPS);

                float* orow = out + (((size_t)(m0 + row) * 36 + p) * 256);
                #pragma unroll
                for (int ntl = 0; ntl < 4; ntl++) {
                    const int col = warp * 32 + ntl * 8 + (lane & 3) * 2;
                    const float2 gvv = *(float2*)&gs[col];
                    const float2 bvv = *(float2*)&bes[col];
                    float2 r;
                    r.x = (acc[mti][ntl][h * 2]     - mu) * rstd * gvv.x + bvv.x;
                    r.y = (acc[mti][ntl][h * 2 + 1] - mu) * rstd * gvv.y + bvv.y;
                    *(float2*)&orow[col] = r;
                }
            }
        // no loop-top sync needed: statb rewrite (phase b, t+1) is separated from
        // these reads by the prologue-end + 3 chunk barriers of t+1.
    }
}

// ===================== Launch =====================
extern "C" void kernel_launch(void* const* d_in, const int* in_sizes, int n_in,
                              void* d_out, int out_size) {
    const float* x_num = (const float*)d_in[0];
    const int*   x_cat = (const int*)d_in[1];
    const float* W1    = (const float*)d_in[2];
    const float* b1    = (const float*)d_in[3];
    const float* W2    = (const float*)d_in[4];
    const float* b2    = (const float*)d_in[5];
    const float* emb   = (const float*)d_in[6];
    const float* gamma = (const float*)d_in[7];
    const float* beta  = (const float*)d_in[8];
    float* out = (float*)d_out;

    cudaFuncSetAttribute(prep_kernel,
                         cudaFuncAttributeMaxDynamicSharedMemorySize, PREP_SMEM);
    cudaFuncSetAttribute(fused_kernel,
                         cudaFuncAttributeMaxDynamicSharedMemorySize, GEMM_SMEM);

    prep_kernel<<<P_DIM * 4, 256, PREP_SMEM>>>(W2);
    fused_kernel<<<GEMM_CTAS + CAT_CTAS, 256, GEMM_SMEM>>>(
        x_num, x_cat, W1, b1, b2, emb, gamma, beta, out);
}

// round 15
// speedup vs baseline: 1.0680x; 1.0680x over previous
#include <cuda_runtime.h>
#include <cuda_fp16.h>
#include <cstdint>

// ===================== Problem constants =====================
#define B_DIM 8192
#define P_DIM 24
#define Q_DIM 12
#define E_DIM 256
#define V_DIM 1000
#define LN_EPS 1e-5f

#define GEMM_CTAS 768          // 24 p * 32 mslots; each CTA: 4 tiles of 64 rows
#define CAT_CTAS 384
#define TOK_PER_CAT_CTA 256    // 98304 / 384

// fragment-packed W2: [p][ks(16)][ntp(16)][lane(32)] uint4  (3.1 MB)
__device__ uint4 g_W2Tf[P_DIM * 16 * 16 * 32];

// ===================== Prep kernel: W2 -> fragment-packed fp16 (direct) =====================
#define PREP_SMEM 65536
__global__ __launch_bounds__(256)
void prep_kernel(const float* __restrict__ W2) {
    extern __shared__ float sm[];          // [64][256] fp32 slice
    const int p  = blockIdx.x >> 2;
    const int sl = blockIdx.x & 3;
    const int e0 = sl * 64;
    const int tid = threadIdx.x;

    #pragma unroll 4
    for (int it = 0; it < 64; it++)
        sm[it * 256 + tid] = W2[((size_t)p * 256 + e0 + it) * 256 + tid];
    __syncthreads();

    const int lane = tid & 31;
    const int warp = tid >> 5;             // 0..7
    const int ksl  = warp & 3;
    const int ks   = sl * 4 + ksl;
    const int ntp0 = (warp >> 2) * 8;
    const int ne_b = lane >> 2;
    const int el0  = ksl * 16 + 2 * (lane & 3);   // local e of kh0 pair

    uint4* dstb = g_W2Tf + (size_t)p * 8192;
    #pragma unroll
    for (int j = 0; j < 8; j++) {
        const int ntp = ntp0 + j;
        const int ne = 2 * ntp * 8 + ne_b;
        const int no = ne + 8;
        uint4 v;
        __half2 h;
        h = __floats2half2_rn(sm[el0 * 256 + ne],       sm[(el0 + 1) * 256 + ne]);
        v.x = *reinterpret_cast<uint32_t*>(&h);
        h = __floats2half2_rn(sm[(el0 + 8) * 256 + ne], sm[(el0 + 9) * 256 + ne]);
        v.y = *reinterpret_cast<uint32_t*>(&h);
        h = __floats2half2_rn(sm[el0 * 256 + no],       sm[(el0 + 1) * 256 + no]);
        v.z = *reinterpret_cast<uint32_t*>(&h);
        h = __floats2half2_rn(sm[(el0 + 8) * 256 + no], sm[(el0 + 9) * 256 + no]);
        v.w = *reinterpret_cast<uint32_t*>(&h);
        dstb[(ks * 16 + ntp) * 32 + lane] = v;
    }
}

// ---- fast gelu (validated: rel_err identical to erff version) ----
__device__ __forceinline__ float fast_gelu(float t) {
    const float z  = fabsf(t) * 0.70710678118654752f;
    const float k  = __fdividef(1.0f, fmaf(0.3275911f, z, 1.0f));
    float pk = fmaf(1.061405429f, k, -1.453152027f);
    pk = fmaf(pk, k, 1.421413741f);
    pk = fmaf(pk, k, -0.284496736f);
    pk = fmaf(pk, k, 0.254829592f);
    pk = pk * k;
    const float ez   = __expf(-z * z);
    const float erfv = fmaf(-pk, ez, 1.0f);
    const float e    = (t >= 0.f) ? erfv : -erfv;
    return 0.5f * t * (1.0f + e);
}

// ===================== Fused kernel: 256 threads, 2 CTAs/SM =====================
// SMEM byte offsets
#define SM_X    0        // 256 f (all 4 tiles' xs)
#define SM_W1   1024     // 256 f
#define SM_B1   2048
#define SM_B2   3072
#define SM_G    4096
#define SM_BE   5120
#define SM_STAT 6144     // 64 rows x 16 f = 4096 B (ends 10240)
#define SM_A    12288    // 32768 B : A frags [ks(16)][mti(4)][lane(32)] uint4
#define GEMM_SMEM 45056

__device__ __forceinline__ void mma16816(float* c, const uint32_t* a, const uint32_t* b) {
    asm volatile(
        "mma.sync.aligned.m16n8k16.row.col.f32.f16.f16.f32 "
        "{%0,%1,%2,%3}, {%4,%5,%6,%7}, {%8,%9}, {%0,%1,%2,%3};\n"
        : "+f"(c[0]), "+f"(c[1]), "+f"(c[2]), "+f"(c[3])
        : "r"(a[0]), "r"(a[1]), "r"(a[2]), "r"(a[3]), "r"(b[0]), "r"(b[1]));
}

__global__ __launch_bounds__(256, 2)
void fused_kernel(const float* __restrict__ x_num,
                  const int*   __restrict__ x_cat,
                  const float* __restrict__ W1,
                  const float* __restrict__ b1,
                  const float* __restrict__ b2,
                  const float* __restrict__ emb,
                  const float* __restrict__ gamma,
                  const float* __restrict__ beta,
                  float* __restrict__ out) {
    const int tid  = threadIdx.x;
    const int lane = tid & 31;
    const int warp = tid >> 5;       // 0..7

    // ================= CAT PATH: 2 independent tokens per warp-iter =================
    if (blockIdx.x >= GEMM_CTAS) {
        const int blk2 = blockIdx.x - GEMM_CTAS;
        const float4* g4  = (const float4*)gamma;
        const float4* be4 = (const float4*)beta;
        float4 g0 = g4[lane], g1 = g4[lane + 32];
        float4 e0 = be4[lane], e1 = be4[lane + 32];

        #pragma unroll 1
        for (int it = 0; it < TOK_PER_CAT_CTA / 16; it++) {
            const int tokA = blk2 * TOK_PER_CAT_CTA + it * 16 + warp * 2;
            const int tokB = tokA + 1;
            const int bA = tokA / Q_DIM, qA = tokA % Q_DIM;
            const int bB = tokB / Q_DIM, qB = tokB % Q_DIM;
            const int idxA = x_cat[(size_t)bA * Q_DIM + qA];
            const int idxB = x_cat[(size_t)bB * Q_DIM + qB];
            const float4* srcA = (const float4*)(emb + ((size_t)qA * V_DIM + idxA) * E_DIM);
            const float4* srcB = (const float4*)(emb + ((size_t)qB * V_DIM + idxB) * E_DIM);
            float4 a0 = srcA[lane], a1 = srcA[lane + 32];
            float4 c0 = srcB[lane], c1 = srcB[lane + 32];

            float sa = a0.x + a0.y + a0.z + a0.w + a1.x + a1.y + a1.z + a1.w;
            float qa = a0.x * a0.x + a0.y * a0.y + a0.z * a0.z + a0.w * a0.w
                     + a1.x * a1.x + a1.y * a1.y + a1.z * a1.z + a1.w * a1.w;
            float sb = c0.x + c0.y + c0.z + c0.w + c1.x + c1.y + c1.z + c1.w;
            float qb = c0.x * c0.x + c0.y * c0.y + c0.z * c0.z + c0.w * c0.w
                     + c1.x * c1.x + c1.y * c1.y + c1.z * c1.z + c1.w * c1.w;
            #pragma unroll
            for (int off = 16; off > 0; off >>= 1) {
                sa += __shfl_xor_sync(0xFFFFFFFFu, sa, off);
                qa += __shfl_xor_sync(0xFFFFFFFFu, qa, off);
                sb += __shfl_xor_sync(0xFFFFFFFFu, sb, off);
                qb += __shfl_xor_sync(0xFFFFFFFFu, qb, off);
            }
            const float muA = sa * (1.0f / 256.0f);
            const float rsA = rsqrtf(qa * (1.0f / 256.0f) - muA * muA + LN_EPS);
            const float muB = sb * (1.0f / 256.0f);
            const float rsB = rsqrtf(qb * (1.0f / 256.0f) - muB * muB + LN_EPS);

            float4 r0, r1;
            r0.x = (a0.x - muA) * rsA * g0.x + e0.x;
            r0.y = (a0.y - muA) * rsA * g0.y + e0.y;
            r0.z = (a0.z - muA) * rsA * g0.z + e0.z;
            r0.w = (a0.w - muA) * rsA * g0.w + e0.w;
            r1.x = (a1.x - muA) * rsA * g1.x + e1.x;
            r1.y = (a1.y - muA) * rsA * g1.y + e1.y;
            r1.z = (a1.z - muA) * rsA * g1.z + e1.z;
            r1.w = (a1.w - muA) * rsA * g1.w + e1.w;
            float4* dstA = (float4*)(out + ((size_t)bA * 36 + 24 + qA) * E_DIM);
            dstA[lane] = r0;
            dstA[lane + 32] = r1;

            r0.x = (c0.x - muB) * rsB * g0.x + e0.x;
            r0.y = (c0.y - muB) * rsB * g0.y + e0.y;
            r0.z = (c0.z - muB) * rsB * g0.z + e0.z;
            r0.w = (c0.w - muB) * rsB * g0.w + e0.w;
            r1.x = (c1.x - muB) * rsB * g1.x + e1.x;
            r1.y = (c1.y - muB) * rsB * g1.y + e1.y;
            r1.z = (c1.z - muB) * rsB * g1.z + e1.z;
            r1.w = (c1.w - muB) * rsB * g1.w + e1.w;
            float4* dstB = (float4*)(out + ((size_t)bB * 36 + 24 + qB) * E_DIM);
            dstB[lane] = r0;
            dstB[lane + 32] = r1;
        }
        return;
    }

    // ================= GEMM PATH =================
    extern __shared__ char smem[];
    const int p     = blockIdx.x >> 5;   // 0..23
    const int mslot = blockIdx.x & 31;   // 0..31

    float* xs_all = (float*)(smem + SM_X);            // [4][64]
    float* w1s = (float*)(smem + SM_W1);
    float* b1s = (float*)(smem + SM_B1);
    float* b2s = (float*)(smem + SM_B2);
    float* gs  = (float*)(smem + SM_G);
    float* bes = (float*)(smem + SM_BE);
    float* statb = (float*)(smem + SM_STAT);          // [64][16]
    uint4* afrag = (uint4*)(smem + SM_A);

    xs_all[tid] = x_num[(size_t)(mslot * 256 + tid) * P_DIM + p];
    w1s[tid] = W1[p * 256 + tid];
    b1s[tid] = b1[p * 256 + tid];
    b2s[tid] = b2[p * 256 + tid];
    gs[tid]  = gamma[tid];
    bes[tid] = beta[tid];

    // B fragments: read directly from gmem (L1-resident, 64 KB per p,
    // shared by the two co-resident CTAs which have the same p).
    const uint4* w2f = g_W2Tf + (size_t)p * 8192;

    float2 b2v[4];
    #pragma unroll
    for (int ntl = 0; ntl < 4; ntl++)
        b2v[ntl] = *(float2*)&b2[p * 256 + warp * 32 + ntl * 8 + (lane & 3) * 2];

    __syncthreads();     // consts + xs visible

    // ---- Tile loop: 4 tiles of 64 rows ----
    for (int t = 0; t < 4; t++) {
        const int m0 = (mslot * 4 + t) * 64;
        const float* xs = xs_all + t * 64;

        // ---- Prologue: gelu -> A frags (warp covers ks = warp, warp+8) ----
        // (prev tile's A reads complete: ordered by the stats barrier of tile t-1)
        #pragma unroll
        for (int kk = 0; kk < 2; kk++) {
            const int ks = warp + kk * 8;
            const int kbase = ks * 16 + (lane & 3) * 2;
            #pragma unroll
            for (int mti = 0; mti < 4; mti++) {
                const float xm0 = xs[mti * 16 + (lane >> 2)];
                const float xm1 = xs[mti * 16 + (lane >> 2) + 8];
                uint32_t r[4];
                #pragma unroll
                for (int reg = 0; reg < 4; reg++) {
                    const float xm = (reg & 1) ? xm1 : xm0;
                    const int k = kbase + (reg & 2) * 4;
                    float h0 = fast_gelu(fmaf(xm, w1s[k],     b1s[k]));
                    float h1 = fast_gelu(fmaf(xm, w1s[k + 1], b1s[k + 1]));
                    __half2 hv = __floats2half2_rn(h0, h1);
                    r[reg] = *reinterpret_cast<uint32_t*>(&hv);
                }
                afrag[(ks * 4 + mti) * 32 + lane] = make_uint4(r[0], r[1], r[2], r[3]);
            }
        }
        __syncthreads();                 // A ready

        // ---- Mainloop: A from SMEM, B via LDG (L1-hit) ----
        float acc[4][4][4];
        #pragma unroll
        for (int i = 0; i < 4; i++)
            #pragma unroll
            for (int j = 0; j < 4; j++)
                #pragma unroll
                for (int r = 0; r < 4; r++) acc[i][j][r] = 0.f;

        const uint4* bg = w2f + warp * 2 * 32 + lane;   // (ks*16 + warp*2 + i)*32 + lane
        #pragma unroll
        for (int ks = 0; ks < 16; ks++) {
            uint4 bv0 = bg[(ks * 16 + 0) * 32];
            uint4 bv1 = bg[(ks * 16 + 1) * 32];
            uint32_t a[4][4];
            #pragma unroll
            for (int mti = 0; mti < 4; mti++) {
                uint4 v = afrag[(ks * 4 + mti) * 32 + lane];
                a[mti][0] = v.x; a[mti][1] = v.y; a[mti][2] = v.z; a[mti][3] = v.w;
            }
            uint32_t b00[2] = {bv0.x, bv0.y};
            uint32_t b01[2] = {bv0.z, bv0.w};
            uint32_t b10[2] = {bv1.x, bv1.y};
            uint32_t b11[2] = {bv1.z, bv1.w};
            #pragma unroll
            for (int mti = 0; mti < 4; mti++) {
                mma16816(acc[mti][0], a[mti], b00);
                mma16816(acc[mti][1], a[mti], b01);
                mma16816(acc[mti][2], a[mti], b10);
                mma16816(acc[mti][3], a[mti], b11);
            }
        }

        // ---- Epilogue: +b2, LayerNorm ----
        #pragma unroll
        for (int mti = 0; mti < 4; mti++)
            #pragma unroll
            for (int ntl = 0; ntl < 4; ntl++) {
                acc[mti][ntl][0] += b2v[ntl].x;
                acc[mti][ntl][1] += b2v[ntl].y;
                acc[mti][ntl][2] += b2v[ntl].x;
                acc[mti][ntl][3] += b2v[ntl].y;
            }

        #pragma unroll
        for (int mti = 0; mti < 4; mti++)
            #pragma unroll
            for (int h = 0; h < 2; h++) {
                float s = 0.f, q = 0.f;
                #pragma unroll
                for (int ntl = 0; ntl < 4; ntl++) {
                    float v0 = acc[mti][ntl][h * 2];
                    float v1 = acc[mti][ntl][h * 2 + 1];
                    s += v0 + v1;
                    q += v0 * v0 + v1 * v1;
                }
                s += __shfl_xor_sync(0xFFFFFFFFu, s, 1);
                q += __shfl_xor_sync(0xFFFFFFFFu, q, 1);
                s += __shfl_xor_sync(0xFFFFFFFFu, s, 2);
                q += __shfl_xor_sync(0xFFFFFFFFu, q, 2);
                if ((lane & 3) == 0) {
                    const int row = mti * 16 + (lane >> 2) + h * 8;
                    *(float2*)&statb[row * 16 + warp * 2] = make_float2(s, q);
                }
            }
        __syncthreads();                 // stats visible; orders A reads vs next prologue

        #pragma unroll
        for (int mti = 0; mti < 4; mti++)
            #pragma unroll
            for (int h = 0; h < 2; h++) {
                const int row = mti * 16 + (lane >> 2) + h * 8;
                float sum = 0.f, sq = 0.f;
                #pragma unroll
                for (int j = 0; j < 4; j++) {
                    float4 v = *(float4*)&statb[row * 16 + j * 4];
                    sum += v.x + v.z;
                    sq  += v.y + v.w;
                }
                const float mu   = sum * (1.0f / 256.0f);
                const float var  = sq * (1.0f / 256.0f) - mu * mu;
                const float rstd = rsqrtf(var + LN_EPS);

                float* orow = out + (((size_t)(m0 + row) * 36 + p) * 256);
                #pragma unroll
                for (int ntl = 0; ntl < 4; ntl++) {
                    const int col = warp * 32 + ntl * 8 + (lane & 3) * 2;
                    const float2 gvv = *(float2*)&gs[col];
                    const float2 bvv = *(float2*)&bes[col];
                    float2 r;
                    r.x = (acc[mti][ntl][h * 2]     - mu) * rstd * gvv.x + bvv.x;
                    r.y = (acc[mti][ntl][h * 2 + 1] - mu) * rstd * gvv.y + bvv.y;
                    *(float2*)&orow[col] = r;
                }
            }
        // statb rewrite (tile t+1) is separated from these reads by the
        // A-ready barrier of tile t+1.
    }
}

// ===================== Launch =====================
extern "C" void kernel_launch(void* const* d_in, const int* in_sizes, int n_in,
                              void* d_out, int out_size) {
    const float* x_num = (const float*)d_in[0];
    const int*   x_cat = (const int*)d_in[1];
    const float* W1    = (const float*)d_in[2];
    const float* b1    = (const float*)d_in[3];
    const float* W2    = (const float*)d_in[4];
    const float* b2    = (const float*)d_in[5];
    const float* emb   = (const float*)d_in[6];
    const float* gamma = (const float*)d_in[7];
    const float* beta  = (const float*)d_in[8];
    float* out = (float*)d_out;

    cudaFuncSetAttribute(prep_kernel,
                         cudaFuncAttributeMaxDynamicSharedMemorySize, PREP_SMEM);
    cudaFuncSetAttribute(fused_kernel,
                         cudaFuncAttributeMaxDynamicSharedMemorySize, GEMM_SMEM);

    prep_kernel<<<P_DIM * 4, 256, PREP_SMEM>>>(W2);
    fused_kernel<<<GEMM_CTAS + CAT_CTAS, 256, GEMM_SMEM>>>(
        x_num, x_cat, W1, b1, b2, emb, gamma, beta, out);
}

// round 16
// speedup vs baseline: 1.1292x; 1.0573x over previous
#include <cuda_runtime.h>
#include <cuda_fp16.h>
#include <cstdint>

// ===================== Problem constants =====================
#define B_DIM 8192
#define P_DIM 24
#define Q_DIM 12
#define E_DIM 256
#define V_DIM 1000
#define LN_EPS 1e-5f

#define GEMM_CTAS 768          // 24 p * 32 mslots; each CTA: 4 tiles of 64 rows
#define CAT_CTAS 384
#define TOK_PER_CAT_CTA 256    // 98304 / 384

// fragment-packed W2: [p][ks(16)][ntp(16)][lane(32)] uint4  (3.1 MB)
__device__ uint4 g_W2Tf[P_DIM * 16 * 16 * 32];

// ===================== Prep kernel: W2 -> fragment-packed fp16 (direct) =====================
#define PREP_SMEM 65536
__global__ __launch_bounds__(256)
void prep_kernel(const float* __restrict__ W2) {
    extern __shared__ float sm[];          // [64][256] fp32 slice
    const int p  = blockIdx.x >> 2;
    const int sl = blockIdx.x & 3;
    const int e0 = sl * 64;
    const int tid = threadIdx.x;

    #pragma unroll 4
    for (int it = 0; it < 64; it++)
        sm[it * 256 + tid] = W2[((size_t)p * 256 + e0 + it) * 256 + tid];
    __syncthreads();

    const int lane = tid & 31;
    const int warp = tid >> 5;             // 0..7
    const int ksl  = warp & 3;
    const int ks   = sl * 4 + ksl;
    const int ntp0 = (warp >> 2) * 8;
    const int ne_b = lane >> 2;
    const int el0  = ksl * 16 + 2 * (lane & 3);   // local e of kh0 pair

    uint4* dstb = g_W2Tf + (size_t)p * 8192;
    #pragma unroll
    for (int j = 0; j < 8; j++) {
        const int ntp = ntp0 + j;
        const int ne = 2 * ntp * 8 + ne_b;
        const int no = ne + 8;
        uint4 v;
        __half2 h;
        h = __floats2half2_rn(sm[el0 * 256 + ne],       sm[(el0 + 1) * 256 + ne]);
        v.x = *reinterpret_cast<uint32_t*>(&h);
        h = __floats2half2_rn(sm[(el0 + 8) * 256 + ne], sm[(el0 + 9) * 256 + ne]);
        v.y = *reinterpret_cast<uint32_t*>(&h);
        h = __floats2half2_rn(sm[el0 * 256 + no],       sm[(el0 + 1) * 256 + no]);
        v.z = *reinterpret_cast<uint32_t*>(&h);
        h = __floats2half2_rn(sm[(el0 + 8) * 256 + no], sm[(el0 + 9) * 256 + no]);
        v.w = *reinterpret_cast<uint32_t*>(&h);
        dstb[(ks * 16 + ntp) * 32 + lane] = v;
    }
}

// ===================== Packed f32x2 gelu =====================
typedef unsigned long long u64;

#define FMA2(d, a, b, c) asm("fma.rn.f32x2 %0, %1, %2, %3;" : "=l"(d) : "l"(a), "l"(b), "l"(c))
#define MUL2(d, a, b)    asm("mul.rn.f32x2 %0, %1, %2;"     : "=l"(d) : "l"(a), "l"(b))
#define ADD2(d, a, b)    asm("add.rn.f32x2 %0, %1, %2;"     : "=l"(d) : "l"(a), "l"(b))

__device__ __forceinline__ u64 pkc(float v) {
    uint32_t u = __float_as_uint(v);
    return (u64)u | ((u64)u << 32);
}

// gelu on a packed pair (same A&S 7.1.26 math as the validated scalar version)
__device__ __forceinline__ u64 gelu2_pk(u64 t2) {
    const u64 abs2 = t2 & 0x7FFFFFFF7FFFFFFFull;
    u64 z, kd, pk, zz, arg, pe, erf2, onepe, th, h2, k2, ez2;
    MUL2(z, abs2, pkc(0.70710678118654752f));
    FMA2(kd, z, pkc(0.3275911f), pkc(1.0f));
    float klo, khi, rlo, rhi;
    asm("mov.b64 {%0, %1}, %2;" : "=f"(klo), "=f"(khi) : "l"(kd));
    asm("rcp.approx.f32 %0, %1;" : "=f"(rlo) : "f"(klo));
    asm("rcp.approx.f32 %0, %1;" : "=f"(rhi) : "f"(khi));
    asm("mov.b64 %0, {%1, %2};" : "=l"(k2) : "f"(rlo), "f"(rhi));
    FMA2(pk, pkc(1.061405429f), k2, pkc(-1.453152027f));
    FMA2(pk, pk, k2, pkc(1.421413741f));
    FMA2(pk, pk, k2, pkc(-0.284496736f));
    FMA2(pk, pk, k2, pkc(0.254829592f));
    MUL2(pk, pk, k2);
    MUL2(zz, z, z);
    MUL2(arg, zz, pkc(-1.4426950408889634f));     // -z^2 * log2(e)
    float alo, ahi, elo, ehi;
    asm("mov.b64 {%0, %1}, %2;" : "=f"(alo), "=f"(ahi) : "l"(arg));
    asm("ex2.approx.f32 %0, %1;" : "=f"(elo) : "f"(alo));
    asm("ex2.approx.f32 %0, %1;" : "=f"(ehi) : "f"(ahi));
    asm("mov.b64 %0, {%1, %2};" : "=l"(ez2) : "f"(elo), "f"(ehi));
    MUL2(pe, pk, ez2);
    FMA2(erf2, pe, pkc(-1.0f), pkc(1.0f));        // erf(|t|/sqrt2), >= 0
    const u64 e2 = erf2 | (t2 & 0x8000000080000000ull);   // copysign from t
    ADD2(onepe, e2, pkc(1.0f));
    MUL2(th, t2, pkc(0.5f));
    MUL2(h2, onepe, th);
    return h2;
}

// ===================== Fused kernel: 256 threads, 2 CTAs/SM =====================
// SMEM byte offsets
#define SM_X    0        // 256 f (all 4 tiles' xs)
#define SM_W1   1024     // 256 f
#define SM_B1   2048
#define SM_B2   3072
#define SM_G    4096
#define SM_BE   5120
#define SM_STAT 6144     // 64 rows x 16 f = 4096 B (ends 10240)
#define SM_A    12288    // 32768 B : A frags [ks(16)][mti(4)][lane(32)] uint4
#define GEMM_SMEM 45056

__device__ __forceinline__ void mma16816(float* c, const uint32_t* a, const uint32_t* b) {
    asm volatile(
        "mma.sync.aligned.m16n8k16.row.col.f32.f16.f16.f32 "
        "{%0,%1,%2,%3}, {%4,%5,%6,%7}, {%8,%9}, {%0,%1,%2,%3};\n"
        : "+f"(c[0]), "+f"(c[1]), "+f"(c[2]), "+f"(c[3])
        : "r"(a[0]), "r"(a[1]), "r"(a[2]), "r"(a[3]), "r"(b[0]), "r"(b[1]));
}

__global__ __launch_bounds__(256, 2)
void fused_kernel(const float* __restrict__ x_num,
                  const int*   __restrict__ x_cat,
                  const float* __restrict__ W1,
                  const float* __restrict__ b1,
                  const float* __restrict__ b2,
                  const float* __restrict__ emb,
                  const float* __restrict__ gamma,
                  const float* __restrict__ beta,
                  float* __restrict__ out) {
    const int tid  = threadIdx.x;
    const int lane = tid & 31;
    const int warp = tid >> 5;       // 0..7

    // ================= CAT PATH: 2 independent tokens per warp-iter =================
    if (blockIdx.x >= GEMM_CTAS) {
        const int blk2 = blockIdx.x - GEMM_CTAS;
        const float4* g4  = (const float4*)gamma;
        const float4* be4 = (const float4*)beta;
        float4 g0 = g4[lane], g1 = g4[lane + 32];
        float4 e0 = be4[lane], e1 = be4[lane + 32];

        #pragma unroll 1
        for (int it = 0; it < TOK_PER_CAT_CTA / 16; it++) {
            const int tokA = blk2 * TOK_PER_CAT_CTA + it * 16 + warp * 2;
            const int tokB = tokA + 1;
            const int bA = tokA / Q_DIM, qA = tokA % Q_DIM;
            const int bB = tokB / Q_DIM, qB = tokB % Q_DIM;
            const int idxA = x_cat[(size_t)bA * Q_DIM + qA];
            const int idxB = x_cat[(size_t)bB * Q_DIM + qB];
            const float4* srcA = (const float4*)(emb + ((size_t)qA * V_DIM + idxA) * E_DIM);
            const float4* srcB = (const float4*)(emb + ((size_t)qB * V_DIM + idxB) * E_DIM);
            float4 a0 = srcA[lane], a1 = srcA[lane + 32];
            float4 c0 = srcB[lane], c1 = srcB[lane + 32];

            float sa = a0.x + a0.y + a0.z + a0.w + a1.x + a1.y + a1.z + a1.w;
            float qa = a0.x * a0.x + a0.y * a0.y + a0.z * a0.z + a0.w * a0.w
                     + a1.x * a1.x + a1.y * a1.y + a1.z * a1.z + a1.w * a1.w;
            float sb = c0.x + c0.y + c0.z + c0.w + c1.x + c1.y + c1.z + c1.w;
            float qb = c0.x * c0.x + c0.y * c0.y + c0.z * c0.z + c0.w * c0.w
                     + c1.x * c1.x + c1.y * c1.y + c1.z * c1.z + c1.w * c1.w;
            #pragma unroll
            for (int off = 16; off > 0; off >>= 1) {
                sa += __shfl_xor_sync(0xFFFFFFFFu, sa, off);
                qa += __shfl_xor_sync(0xFFFFFFFFu, qa, off);
                sb += __shfl_xor_sync(0xFFFFFFFFu, sb, off);
                qb += __shfl_xor_sync(0xFFFFFFFFu, qb, off);
            }
            const float muA = sa * (1.0f / 256.0f);
            const float rsA = rsqrtf(qa * (1.0f / 256.0f) - muA * muA + LN_EPS);
            const float muB = sb * (1.0f / 256.0f);
            const float rsB = rsqrtf(qb * (1.0f / 256.0f) - muB * muB + LN_EPS);

            float4 r0, r1;
            r0.x = (a0.x - muA) * rsA * g0.x + e0.x;
            r0.y = (a0.y - muA) * rsA * g0.y + e0.y;
            r0.z = (a0.z - muA) * rsA * g0.z + e0.z;
            r0.w = (a0.w - muA) * rsA * g0.w + e0.w;
            r1.x = (a1.x - muA) * rsA * g1.x + e1.x;
            r1.y = (a1.y - muA) * rsA * g1.y + e1.y;
            r1.z = (a1.z - muA) * rsA * g1.z + e1.z;
            r1.w = (a1.w - muA) * rsA * g1.w + e1.w;
            float4* dstA = (float4*)(out + ((size_t)bA * 36 + 24 + qA) * E_DIM);
            dstA[lane] = r0;
            dstA[lane + 32] = r1;

            r0.x = (c0.x - muB) * rsB * g0.x + e0.x;
            r0.y = (c0.y - muB) * rsB * g0.y + e0.y;
            r0.z = (c0.z - muB) * rsB * g0.z + e0.z;
            r0.w = (c0.w - muB) * rsB * g0.w + e0.w;
            r1.x = (c1.x - muB) * rsB * g1.x + e1.x;
            r1.y = (c1.y - muB) * rsB * g1.y + e1.y;
            r1.z = (c1.z - muB) * rsB * g1.z + e1.z;
            r1.w = (c1.w - muB) * rsB * g1.w + e1.w;
            float4* dstB = (float4*)(out + ((size_t)bB * 36 + 24 + qB) * E_DIM);
            dstB[lane] = r0;
            dstB[lane + 32] = r1;
        }
        return;
    }

    // ================= GEMM PATH =================
    extern __shared__ char smem[];
    const int p     = blockIdx.x >> 5;   // 0..23
    const int mslot = blockIdx.x & 31;   // 0..31

    float* xs_all = (float*)(smem + SM_X);            // [4][64]
    float* w1s = (float*)(smem + SM_W1);
    float* b1s = (float*)(smem + SM_B1);
    float* b2s = (float*)(smem + SM_B2);
    float* gs  = (float*)(smem + SM_G);
    float* bes = (float*)(smem + SM_BE);
    float* statb = (float*)(smem + SM_STAT);          // [64][16]
    uint4* afrag = (uint4*)(smem + SM_A);

    xs_all[tid] = x_num[(size_t)(mslot * 256 + tid) * P_DIM + p];
    w1s[tid] = W1[p * 256 + tid];
    b1s[tid] = b1[p * 256 + tid];
    b2s[tid] = b2[p * 256 + tid];
    gs[tid]  = gamma[tid];
    bes[tid] = beta[tid];

    // B fragments: read directly from gmem (L1-resident, 64 KB per p).
    const uint4* w2f = g_W2Tf + (size_t)p * 8192;

    float2 b2v[4];
    #pragma unroll
    for (int ntl = 0; ntl < 4; ntl++)
        b2v[ntl] = *(float2*)&b2[p * 256 + warp * 32 + ntl * 8 + (lane & 3) * 2];

    __syncthreads();     // consts + xs visible

    // ---- Tile loop: 4 tiles of 64 rows ----
    for (int t = 0; t < 4; t++) {
        const int m0 = (mslot * 4 + t) * 64;
        const float* xs = xs_all + t * 64;

        // ---- Prologue: packed-f32x2 gelu -> A frags (warp covers ks = warp, warp+8) ----
        #pragma unroll
        for (int kk = 0; kk < 2; kk++) {
            const int ks = warp + kk * 8;
            const int kbase = ks * 16 + (lane & 3) * 2;
            #pragma unroll
            for (int mti = 0; mti < 4; mti++) {
                const float xm0 = xs[mti * 16 + (lane >> 2)];
                const float xm1 = xs[mti * 16 + (lane >> 2) + 8];
                uint32_t r[4];
                #pragma unroll
                for (int reg = 0; reg < 4; reg++) {
                    const float xm = (reg & 1) ? xm1 : xm0;
                    const int k = kbase + (reg & 2) * 4;     // even -> 8B-aligned pair
                    u64 xm2;
                    asm("mov.b64 %0, {%1, %1};" : "=l"(xm2) : "f"(xm));
                    const u64 w12 = *(const u64*)&w1s[k];
                    const u64 b12 = *(const u64*)&b1s[k];
                    u64 t2;
                    FMA2(t2, xm2, w12, b12);
                    const u64 h2 = gelu2_pk(t2);
                    float hlo, hhi;
                    asm("mov.b64 {%0, %1}, %2;" : "=f"(hlo), "=f"(hhi) : "l"(h2));
                    __half2 hv = __floats2half2_rn(hlo, hhi);
                    r[reg] = *reinterpret_cast<uint32_t*>(&hv);
                }
                afrag[(ks * 4 + mti) * 32 + lane] = make_uint4(r[0], r[1], r[2], r[3]);
            }
        }
        __syncthreads();                 // A ready

        // ---- Mainloop: A from SMEM, B via LDG (L1-hit) ----
        float acc[4][4][4];
        #pragma unroll
        for (int i = 0; i < 4; i++)
            #pragma unroll
            for (int j = 0; j < 4; j++)
                #pragma unroll
                for (int r = 0; r < 4; r++) acc[i][j][r] = 0.f;

        const uint4* bg = w2f + warp * 2 * 32 + lane;   // (ks*16 + warp*2 + i)*32 + lane
        #pragma unroll
        for (int ks = 0; ks < 16; ks++) {
            uint4 bv0 = bg[(ks * 16 + 0) * 32];
            uint4 bv1 = bg[(ks * 16 + 1) * 32];
            uint32_t a[4][4];
            #pragma unroll
            for (int mti = 0; mti < 4; mti++) {
                uint4 v = afrag[(ks * 4 + mti) * 32 + lane];
                a[mti][0] = v.x; a[mti][1] = v.y; a[mti][2] = v.z; a[mti][3] = v.w;
            }
            uint32_t b00[2] = {bv0.x, bv0.y};
            uint32_t b01[2] = {bv0.z, bv0.w};
            uint32_t b10[2] = {bv1.x, bv1.y};
            uint32_t b11[2] = {bv1.z, bv1.w};
            #pragma unroll
            for (int mti = 0; mti < 4; mti++) {
                mma16816(acc[mti][0], a[mti], b00);
                mma16816(acc[mti][1], a[mti], b01);
                mma16816(acc[mti][2], a[mti], b10);
                mma16816(acc[mti][3], a[mti], b11);
            }
        }

        // ---- Epilogue: +b2, LayerNorm ----
        #pragma unroll
        for (int mti = 0; mti < 4; mti++)
            #pragma unroll
            for (int ntl = 0; ntl < 4; ntl++) {
                acc[mti][ntl][0] += b2v[ntl].x;
                acc[mti][ntl][1] += b2v[ntl].y;
                acc[mti][ntl][2] += b2v[ntl].x;
                acc[mti][ntl][3] += b2v[ntl].y;
            }

        #pragma unroll
        for (int mti = 0; mti < 4; mti++)
            #pragma unroll
            for (int h = 0; h < 2; h++) {
                float s = 0.f, q = 0.f;
                #pragma unroll
                for (int ntl = 0; ntl < 4; ntl++) {
                    float v0 = acc[mti][ntl][h * 2];
                    float v1 = acc[mti][ntl][h * 2 + 1];
                    s += v0 + v1;
                    q += v0 * v0 + v1 * v1;
                }
                s += __shfl_xor_sync(0xFFFFFFFFu, s, 1);
                q += __shfl_xor_sync(0xFFFFFFFFu, q, 1);
                s += __shfl_xor_sync(0xFFFFFFFFu, s, 2);
                q += __shfl_xor_sync(0xFFFFFFFFu, q, 2);
                if ((lane & 3) == 0) {
                    const int row = mti * 16 + (lane >> 2) + h * 8;
                    *(float2*)&statb[row * 16 + warp * 2] = make_float2(s, q);
                }
            }
        __syncthreads();                 // stats visible; orders A reads vs next prologue

        #pragma unroll
        for (int mti = 0; mti < 4; mti++)
            #pragma unroll
            for (int h = 0; h < 2; h++) {
                const int row = mti * 16 + (lane >> 2) + h * 8;
                float sum = 0.f, sq = 0.f;
                #pragma unroll
                for (int j = 0; j < 4; j++) {
                    float4 v = *(float4*)&statb[row * 16 + j * 4];
                    sum += v.x + v.z;
                    sq  += v.y + v.w;
                }
                const float mu   = sum * (1.0f / 256.0f);
                const float var  = sq * (1.0f / 256.0f) - mu * mu;
                const float rstd = rsqrtf(var + LN_EPS);

                float* orow = out + (((size_t)(m0 + row) * 36 + p) * 256);
                #pragma unroll
                for (int ntl = 0; ntl < 4; ntl++) {
                    const int col = warp * 32 + ntl * 8 + (lane & 3) * 2;
                    const float2 gvv = *(float2*)&gs[col];
                    const float2 bvv = *(float2*)&bes[col];
                    float2 r;
                    r.x = (acc[mti][ntl][h * 2]     - mu) * rstd * gvv.x + bvv.x;
                    r.y = (acc[mti][ntl][h * 2 + 1] - mu) * rstd * gvv.y + bvv.y;
                    *(float2*)&orow[col] = r;
                }
            }
        // statb rewrite (tile t+1) is separated from these reads by the
        // A-ready barrier of tile t+1.
    }
}

// ===================== Launch =====================
extern "C" void kernel_launch(void* const* d_in, const int* in_sizes, int n_in,
                              void* d_out, int out_size) {
    const float* x_num = (const float*)d_in[0];
    const int*   x_cat = (const int*)d_in[1];
    const float* W1    = (const float*)d_in[2];
    const float* b1    = (const float*)d_in[3];
    const float* W2    = (const float*)d_in[4];
    const float* b2    = (const float*)d_in[5];
    const float* emb   = (const float*)d_in[6];
    const float* gamma = (const float*)d_in[7];
    const float* beta  = (const float*)d_in[8];
    float* out = (float*)d_out;

    cudaFuncSetAttribute(prep_kernel,
                         cudaFuncAttributeMaxDynamicSharedMemorySize, PREP_SMEM);
    cudaFuncSetAttribute(fused_kernel,
                         cudaFuncAttributeMaxDynamicSharedMemorySize, GEMM_SMEM);

    prep_kernel<<<P_DIM * 4, 256, PREP_SMEM>>>(W2);
    fused_kernel<<<GEMM_CTAS + CAT_CTAS, 256, GEMM_SMEM>>>(
        x_num, x_cat, W1, b1, b2, emb, gamma, beta, out);
}